// round 3
// baseline (speedup 1.0000x reference)
#include <cuda_runtime.h>

// Problem constants (fixed by setup_inputs)
#define B_    128
#define A_    30
#define T_    65
#define FIN_  4
#define HID_  64
#define H_    1920           // A_ * HID_
#define G4_   7680           // 4 * H_
#define NSTEP 64             // T_ - 1

// ---------------- scratch (device globals; no allocation allowed) ----------------
__device__ float g_h[2 * B_ * H_];
__device__ float g_c[2 * B_ * H_];
__device__ float g_x[B_ * H_];        // MLP output, [B, H]
__device__ float g_gates[B_ * G4_];   // [B, 4H]
__device__ float g_r3[B_ * H_];       // W3 partial sums (pre-relu, pre-bias)

// ---------------- packed f32x2 helpers (FFMA2 path, sm_103a) ----------------
__device__ __forceinline__ unsigned long long pack2(float lo, float hi) {
    unsigned long long r;
    asm("mov.b64 %0,{%1,%2};" : "=l"(r) : "f"(lo), "f"(hi));
    return r;
}
__device__ __forceinline__ void unpack2(unsigned long long v, float& lo, float& hi) {
    asm("mov.b64 {%0,%1},%2;" : "=f"(lo), "=f"(hi) : "l"(v));
}
__device__ __forceinline__ void ffma2(unsigned long long& d, unsigned long long a, unsigned long long b) {
    asm("fma.rn.f32x2 %0,%1,%2,%0;" : "+l"(d) : "l"(a), "l"(b));
}

// ---------------- fused per-atom MLP (2 layers, relu) + input select ----------------
// grid 960, block (64,4). Row r = b*30+a in [0,3840). xout[r*64 + j].
__global__ void __launch_bounds__(256) mlp_kernel(
    const float* __restrict__ inputs, const float* __restrict__ prev,
    const float* __restrict__ W1, const float* __restrict__ b1,
    const float* __restrict__ W2, const float* __restrict__ b2,
    float* __restrict__ xout, int t, const int* __restrict__ burn)
{
    __shared__ float W1t[4 * 64];     // transposed: W1t[f*64+j]
    __shared__ float W2t[64 * 64];    // transposed: W2t[k*64+j]
    __shared__ float b1s[64], b2s[64];
    __shared__ float ins_s[4][4];
    __shared__ float x1s[4][64];

    const int j  = threadIdx.x;       // 0..63
    const int rl = threadIdx.y;       // 0..3
    const int tid = rl * 64 + j;

    for (int i = tid; i < 64 * 64; i += 256) {
        int jj = i >> 6, kk = i & 63;
        W2t[kk * 64 + jj] = W2[i];
    }
    {   // W1 is 64x4 = 256 elements: one per thread
        int jj = tid >> 2, ff = tid & 3;
        W1t[ff * 64 + jj] = W1[tid];
    }
    if (tid < 64) { b1s[tid] = b1[tid]; b2s[tid] = b2[tid]; }

    if (tid < 16) {
        int bi = burn ? *burn : 20;
        int r = blockIdx.x * 4 + (tid >> 2);
        int f = tid & 3;
        ins_s[tid >> 2][f] = (t <= bi) ? inputs[(r * T_ + t) * FIN_ + f]
                                       : prev[(r * NSTEP + (t - 1)) * FIN_ + f];
    }
    __syncthreads();

    float v = b1s[j];
#pragma unroll
    for (int f = 0; f < 4; f++) v = fmaf(ins_s[rl][f], W1t[f * 64 + j], v);
    v = fmaxf(v, 0.f);
    x1s[rl][j] = v;
    __syncthreads();

    float v2 = b2s[j];
#pragma unroll
    for (int k = 0; k < 64; k++) v2 = fmaf(x1s[rl][k], W2t[k * 64 + j], v2);
    v2 = fmaxf(v2, 0.f);
    xout[(blockIdx.x * 4 + rl) * 64 + j] = v2;
}

// ---------------- M=128 GEMM: C[128,N] = A0@W0^T (+ A1@W1^T) (+bias0+bias1) ----------------
// W row-major [N,K]; A row-major [128,K]. BM=128, BN=64, BK=16, 256 threads.
// Per thread 8 (m, as 4 f32x2 pairs) x 4 (n) via fma.rn.f32x2.
// atomicMode=1: atomicAdd into C (split-K), no bias.
#define BK_    16
#define XS_LD  130
#define WS_LD  68

__global__ void __launch_bounds__(256) gemm128(
    float* __restrict__ C,
    const float* __restrict__ Aa, const float* __restrict__ Wa,
    const float* __restrict__ Ab, const float* __restrict__ Wb,
    const float* __restrict__ bias0, const float* __restrict__ bias1,
    int N, int K, int kchunk, int atomicMode)
{
    __shared__ __align__(16) float Xs[BK_ * XS_LD];
    __shared__ __align__(16) float Ws[BK_ * WS_LD];

    const int tid  = threadIdx.x;
    const int tx   = tid & 15;            // n-group
    const int ty   = tid >> 4;            // m-group
    const int n0   = blockIdx.x * 64;
    const int kbeg = blockIdx.y * kchunk;
    const int kend = min(kbeg + kchunk, K);
    const int lf4  = tid & 3;             // which float4 within a 16-wide k row
    const int lrow = tid >> 2;            // 0..63

    unsigned long long acc[4][4];
#pragma unroll
    for (int i = 0; i < 4; i++)
#pragma unroll
        for (int jj = 0; jj < 4; jj++) acc[i][jj] = 0ULL;

    const int nph = (Ab != nullptr) ? 2 : 1;
    for (int ph = 0; ph < nph; ph++) {
        const float* A = ph ? Ab : Aa;
        const float* W = ph ? Wb : Wa;
        for (int k0 = kbeg; k0 < kend; k0 += BK_) {
            float4 xv0 = *(const float4*)(A + lrow * K + k0 + lf4 * 4);
            float4 xv1 = *(const float4*)(A + (lrow + 64) * K + k0 + lf4 * 4);
            float4 wv  = *(const float4*)(W + (n0 + lrow) * K + k0 + lf4 * 4);
            int kk = lf4 * 4;
            Xs[(kk + 0) * XS_LD + lrow] = xv0.x;
            Xs[(kk + 1) * XS_LD + lrow] = xv0.y;
            Xs[(kk + 2) * XS_LD + lrow] = xv0.z;
            Xs[(kk + 3) * XS_LD + lrow] = xv0.w;
            Xs[(kk + 0) * XS_LD + lrow + 64] = xv1.x;
            Xs[(kk + 1) * XS_LD + lrow + 64] = xv1.y;
            Xs[(kk + 2) * XS_LD + lrow + 64] = xv1.z;
            Xs[(kk + 3) * XS_LD + lrow + 64] = xv1.w;
            Ws[(kk + 0) * WS_LD + lrow] = wv.x;
            Ws[(kk + 1) * WS_LD + lrow] = wv.y;
            Ws[(kk + 2) * WS_LD + lrow] = wv.z;
            Ws[(kk + 3) * WS_LD + lrow] = wv.w;
            __syncthreads();
#pragma unroll
            for (int kk2 = 0; kk2 < BK_; kk2++) {
                unsigned long long a2[4];
#pragma unroll
                for (int mp = 0; mp < 4; mp++)
                    a2[mp] = *(const unsigned long long*)(Xs + kk2 * XS_LD + ty * 8 + mp * 2);
                float4 w4 = *(const float4*)(Ws + kk2 * WS_LD + tx * 4);
                unsigned long long b0 = pack2(w4.x, w4.x);
                unsigned long long b1v = pack2(w4.y, w4.y);
                unsigned long long b2v = pack2(w4.z, w4.z);
                unsigned long long b3v = pack2(w4.w, w4.w);
#pragma unroll
                for (int mp = 0; mp < 4; mp++) {
                    ffma2(acc[mp][0], a2[mp], b0);
                    ffma2(acc[mp][1], a2[mp], b1v);
                    ffma2(acc[mp][2], a2[mp], b2v);
                    ffma2(acc[mp][3], a2[mp], b3v);
                }
            }
            __syncthreads();
        }
    }

#pragma unroll
    for (int jj = 0; jj < 4; jj++) {
        int n = n0 + tx * 4 + jj;
        float bb = 0.f;
        if (bias0) bb += bias0[n];
        if (bias1) bb += bias1[n];
#pragma unroll
        for (int mp = 0; mp < 4; mp++) {
            float lo, hi;
            unpack2(acc[mp][jj], lo, hi);
            int m = ty * 8 + mp * 2;
            if (atomicMode) {
                atomicAdd(C + m * N + n, lo);
                atomicAdd(C + (m + 1) * N + n, hi);
            } else {
                C[m * N + n] = lo + bb;
                C[(m + 1) * N + n] = hi + bb;
            }
        }
    }
}

// ---------------- LSTM cell elementwise (PyTorch gate order i,f,g,o) ----------------
__global__ void __launch_bounds__(256) lstm_cell(
    const float* __restrict__ gates, float* __restrict__ h, float* __restrict__ c)
{
    int idx = blockIdx.x * 256 + threadIdx.x;    // < 128*1920
    int b  = idx / H_;
    int jj = idx - b * H_;
    const float* g = gates + b * G4_;
    float ig = g[jj], fg = g[H_ + jj], gg = g[2 * H_ + jj], og = g[3 * H_ + jj];
    float si = 1.f / (1.f + expf(-ig));
    float sf = 1.f / (1.f + expf(-fg));
    float so = 1.f / (1.f + expf(-og));
    float tg = tanhf(gg);
    float cn = sf * c[idx] + si * tg;
    float hn = so * tanhf(cn);
    c[idx] = cn;
    h[idx] = hn;
}

// ---------------- W4 projection + residual + output write ----------------
// Applies bias3+relu while reading the split-K W3 sums. grid = B_, block = 128.
__global__ void __launch_bounds__(128) w4_kernel(
    const float* __restrict__ r3, const float* __restrict__ b3,
    const float* __restrict__ W4, const float* __restrict__ b4,
    const float* __restrict__ inputs, float* __restrict__ out,
    int t, const int* __restrict__ burn)
{
    __shared__ __align__(16) float xs[H_];
    int b = blockIdx.x, tid = threadIdx.x;
    for (int k = tid; k < H_; k += 128) xs[k] = fmaxf(r3[b * H_ + k] + b3[k], 0.f);
    __syncthreads();
    if (tid < A_ * FIN_) {
        const float4* wp = (const float4*)(W4 + tid * H_);
        const float4* xp = (const float4*)xs;
        float a0 = 0.f, a1 = 0.f, a2 = 0.f, a3 = 0.f;
#pragma unroll 4
        for (int k = 0; k < H_ / 4; k++) {
            float4 w = wp[k]; float4 x = xp[k];
            a0 = fmaf(w.x, x.x, a0); a1 = fmaf(w.y, x.y, a1);
            a2 = fmaf(w.z, x.z, a2); a3 = fmaf(w.w, x.w, a3);
        }
        float acc = b4[tid] + (a0 + a1) + (a2 + a3);
        int a = tid >> 2, f = tid & 3;
        int r = b * A_ + a;
        int bi = burn ? *burn : 20;
        float insv = (t <= bi) ? inputs[(r * T_ + t) * FIN_ + f]
                               : out[(r * NSTEP + t - 1) * FIN_ + f];
        out[(r * NSTEP + t) * FIN_ + f] = acc + insv;
    }
}

// ---------------- launch ----------------
extern "C" void kernel_launch(void* const* d_in, const int* in_sizes, int n_in,
                              void* d_out, int out_size)
{
    const float* inputs = (const float*)d_in[0];
    const float* W1  = (const float*)d_in[1];
    const float* b1  = (const float*)d_in[2];
    const float* W2  = (const float*)d_in[3];
    const float* b2  = (const float*)d_in[4];
    const float* Wih = (const float*)d_in[5];
    const float* Whh = (const float*)d_in[6];
    const float* bih = (const float*)d_in[7];
    const float* bhh = (const float*)d_in[8];
    const float* W3  = (const float*)d_in[9];
    const float* b3  = (const float*)d_in[10];
    const float* W4  = (const float*)d_in[11];
    const float* b4  = (const float*)d_in[12];
    const int* burn  = (n_in > 14) ? (const int*)d_in[14] : nullptr;
    float* out = (float*)d_out;

    void *ph, *pc, *px, *pg, *pr;
    cudaGetSymbolAddress(&ph, g_h);
    cudaGetSymbolAddress(&pc, g_c);
    cudaGetSymbolAddress(&px, g_x);
    cudaGetSymbolAddress(&pg, g_gates);
    cudaGetSymbolAddress(&pr, g_r3);
    float* h0 = (float*)ph;  float* h1 = h0 + B_ * H_;
    float* c0 = (float*)pc;  float* c1 = c0 + B_ * H_;
    float* xm = (float*)px;
    float* gbuf = (float*)pg;
    float* r3 = (float*)pr;

    cudaMemsetAsync(ph, 0, sizeof(float) * 2 * B_ * H_);
    cudaMemsetAsync(pc, 0, sizeof(float) * 2 * B_ * H_);

    const long LW = (long)G4_ * H_;   // per-layer weight stride
    for (int t = 0; t < NSTEP; t++) {
        mlp_kernel<<<960, dim3(64, 4)>>>(inputs, out, W1, b1, W2, b2, xm, t, burn);

        // layer 0: gates = x@Wih0^T + h0@Whh0^T + bih0 + bhh0
        gemm128<<<dim3(G4_ / 64, 1), 256>>>(gbuf, xm, Wih, h0, Whh,
                                            bih, bhh, G4_, H_, H_, 0);
        lstm_cell<<<960, 256>>>(gbuf, h0, c0);

        // layer 1: gates = h0_new@Wih1^T + h1@Whh1^T + bih1 + bhh1
        gemm128<<<dim3(G4_ / 64, 1), 256>>>(gbuf, h0, Wih + LW, h1, Whh + LW,
                                            bih + G4_, bhh + G4_, G4_, H_, H_, 0);
        lstm_cell<<<960, 256>>>(gbuf, h1, c1);

        // W3: split-K=4 with atomic accumulation (bias+relu deferred to w4_kernel)
        cudaMemsetAsync(pr, 0, sizeof(float) * B_ * H_);
        gemm128<<<dim3(H_ / 64, 4), 256>>>(r3, h1, W3, nullptr, nullptr,
                                           nullptr, nullptr, H_, H_, H_ / 4, 1);

        w4_kernel<<<B_, 128>>>(r3, b3, W4, b4, inputs, out, t, burn);
    }
}

// round 5
// speedup vs baseline: 3.1519x; 3.1519x over previous
#include <cuda_runtime.h>
#include <cuda_bf16.h>
#include <cstdint>

// Problem constants
#define B_    128
#define A_    30
#define T_    65
#define FIN_  4
#define H_    1920
#define G4_   7680
#define NSTEP 64

// GEMM tiling: CTA tile 128(M) x 64(N), K chunk = 64
#define KCHUNKS  30                 // 1920/64 per phase
#define NSTG     4                  // pipeline stages
#define STAGE_B  49152              // Ah16K + Al16K + Wh8K + Wl8K
#define SMEMB    (1024 + 1024 + NSTG * STAGE_B)   // align slack + barriers + stages
#define LOFF     14745600u          // per-layer elems in tiled LSTM weights (7680*1920)

// ---------------- device scratch (no allocation allowed) ----------------
__device__ __align__(1024) __nv_bfloat16 g_wih_h[2u*7680u*1920u];
__device__ __align__(1024) __nv_bfloat16 g_wih_l[2u*7680u*1920u];
__device__ __align__(1024) __nv_bfloat16 g_whh_h[2u*7680u*1920u];
__device__ __align__(1024) __nv_bfloat16 g_whh_l[2u*7680u*1920u];
__device__ __align__(1024) __nv_bfloat16 g_w3_h[1920u*1920u];
__device__ __align__(1024) __nv_bfloat16 g_w3_l[1920u*1920u];
__device__ __align__(1024) __nv_bfloat16 g_xh[245760];   // 30 chunks x 8192 (128 rows x 64 k)
__device__ __align__(1024) __nv_bfloat16 g_xl[245760];
__device__ __align__(1024) __nv_bfloat16 g_h0h[245760];
__device__ __align__(1024) __nv_bfloat16 g_h0l[245760];
__device__ __align__(1024) __nv_bfloat16 g_h1h[245760];
__device__ __align__(1024) __nv_bfloat16 g_h1l[245760];
__device__ float g_c[2 * B_ * H_];
__device__ float g_gates[B_ * G4_];
__device__ float g_r3[B_ * H_];

// ---------------- PTX helpers ----------------
__device__ __forceinline__ uint32_t smem_u32(const void* p) {
    uint32_t a;
    asm("{ .reg .u64 t; cvta.to.shared.u64 t, %1; cvt.u32.u64 %0, t; }" : "=r"(a) : "l"(p));
    return a;
}
#define MBAR_INIT(addr, cnt) \
    asm volatile("mbarrier.init.shared.b64 [%0], %1;" :: "r"(addr), "r"((uint32_t)(cnt)) : "memory")
#define MBAR_EXPECT_TX(addr, bytes) \
    asm volatile("mbarrier.arrive.expect_tx.shared.b64 _, [%0], %1;" :: "r"(addr), "r"((uint32_t)(bytes)) : "memory")
#define MBAR_ARRIVE(addr) \
    asm volatile("mbarrier.arrive.shared.b64 _, [%0];" :: "r"(addr) : "memory")
#define MBAR_WAIT(addr, par) do { \
    uint32_t _m=(addr), _p=(par), _d; \
    asm volatile("{\n\t.reg .pred p;\n\tmbarrier.try_wait.parity.acquire.cta.shared::cta.b64 p, [%1], %2;\n\tselp.b32 %0,1,0,p;\n\t}" \
        : "=r"(_d) : "r"(_m), "r"(_p) : "memory"); \
    if (!_d) { \
        asm volatile("{\n\t.reg .pred P1;\n\tWL_%=:\n\tmbarrier.try_wait.parity.acquire.cta.shared::cta.b64 P1, [%0], %1, 0x989680;\n\t@P1 bra.uni WD_%=;\n\tbra.uni WL_%=;\n\tWD_%=:\n\t}" \
            :: "r"(_m), "r"(_p) : "memory"); \
    } } while (0)
#define BULK_G2S(dst, src, bytes, mbar) \
    asm volatile("cp.async.bulk.shared::cluster.global.mbarrier::complete_tx::bytes [%0], [%1], %2, [%3];" \
        :: "r"(dst), "l"(src), "r"((uint32_t)(bytes)), "r"(mbar) : "memory")

#define LDSM4(r, addr) \
    asm volatile("ldmatrix.sync.aligned.m8n8.x4.shared.b16 {%0,%1,%2,%3}, [%4];" \
        : "=r"((r)[0]), "=r"((r)[1]), "=r"((r)[2]), "=r"((r)[3]) : "r"(addr))
#define MMA(d, a, b0v, b1v) \
    asm volatile("mma.sync.aligned.m16n8k16.row.col.f32.bf16.bf16.f32 " \
        "{%0,%1,%2,%3}, {%4,%5,%6,%7}, {%8,%9}, {%0,%1,%2,%3};" \
        : "+f"((d)[0]), "+f"((d)[1]), "+f"((d)[2]), "+f"((d)[3]) \
        : "r"((a)[0]), "r"((a)[1]), "r"((a)[2]), "r"((a)[3]), "r"(b0v), "r"(b1v))

__device__ __forceinline__ uint32_t sw128(uint32_t o) { return o ^ ((o >> 3) & 0x70); }
// activation tile element index (bf16 units): row in [0,128), k in [0,1920)
__device__ __forceinline__ uint32_t act_idx(int row, int k) {
    return (uint32_t)((k >> 6) * 8192) + (sw128((uint32_t)(row * 128 + (k & 63) * 2)) >> 1);
}

// ---------------- weight conversion: fp32 [N,K] -> swizzled bf16 hi/lo 64x64 tiles ----------------
__global__ void __launch_bounds__(256) conv_w(
    const float* __restrict__ src, __nv_bfloat16* __restrict__ hi,
    __nv_bfloat16* __restrict__ lo, int total, int K)
{
    int i = blockIdx.x * 256 + threadIdx.x;
    if (i >= total) return;
    int n = i / K, k = i - n * K;
    float w = src[i];
    __nv_bfloat16 h = __float2bfloat16(w);
    __nv_bfloat16 l = __float2bfloat16(w - __bfloat162float(h));
    uint32_t dst = (uint32_t)((n >> 6) * (K >> 6) + (k >> 6)) * 4096
                 + (sw128((uint32_t)((n & 63) * 128 + (k & 63) * 2)) >> 1);
    hi[dst] = h;
    lo[dst] = l;
}

// ---------------- fused per-atom MLP, writes swizzled hi/lo x ----------------
__global__ void __launch_bounds__(256) mlp_kernel(
    const float* __restrict__ inputs, const float* __restrict__ prev,
    const float* __restrict__ W1, const float* __restrict__ b1,
    const float* __restrict__ W2, const float* __restrict__ b2,
    __nv_bfloat16* __restrict__ xh, __nv_bfloat16* __restrict__ xl,
    int t, const int* __restrict__ burn)
{
    __shared__ float W1t[4 * 64];
    __shared__ float W2t[64 * 64];
    __shared__ float b1s[64], b2s[64];
    __shared__ float ins_s[4][4];
    __shared__ float x1s[4][64];

    const int j  = threadIdx.x;
    const int rl = threadIdx.y;
    const int tid = rl * 64 + j;

    for (int i = tid; i < 64 * 64; i += 256) {
        int jj = i >> 6, kk = i & 63;
        W2t[kk * 64 + jj] = W2[i];
    }
    { int jj = tid >> 2, ff = tid & 3; W1t[ff * 64 + jj] = W1[tid]; }
    if (tid < 64) { b1s[tid] = b1[tid]; b2s[tid] = b2[tid]; }
    if (tid < 16) {
        int bi = burn ? *burn : 20;
        int r = blockIdx.x * 4 + (tid >> 2);
        int f = tid & 3;
        ins_s[tid >> 2][f] = (t <= bi) ? inputs[(r * T_ + t) * FIN_ + f]
                                       : prev[(r * NSTEP + (t - 1)) * FIN_ + f];
    }
    __syncthreads();

    float v = b1s[j];
#pragma unroll
    for (int f = 0; f < 4; f++) v = fmaf(ins_s[rl][f], W1t[f * 64 + j], v);
    v = fmaxf(v, 0.f);
    x1s[rl][j] = v;
    __syncthreads();

    float v2 = b2s[j];
#pragma unroll
    for (int k = 0; k < 64; k++) v2 = fmaf(x1s[rl][k], W2t[k * 64 + j], v2);
    v2 = fmaxf(v2, 0.f);

    int r = blockIdx.x * 4 + rl;
    int bb = r / A_, a = r - bb * A_;
    uint32_t ai = act_idx(bb, a * 64 + j);
    __nv_bfloat16 hv = __float2bfloat16(v2);
    xh[ai] = hv;
    xl[ai] = __float2bfloat16(v2 - __bfloat162float(hv));
}

// ---------------- mma.sync GEMM: C[128, nt*64..] = sum_ph A_ph @ W_ph^T (+bias) ----------------
// hi/lo split: D += Ah*Wh + Ah*Wl + Al*Wh, fp32 accumulate in registers.
__global__ void __launch_bounds__(256, 1) gemm_mma(
    float* __restrict__ C, int ldc,
    const __nv_bfloat16* __restrict__ A0h, const __nv_bfloat16* __restrict__ A0l,
    const __nv_bfloat16* __restrict__ W0h, const __nv_bfloat16* __restrict__ W0l,
    const __nv_bfloat16* __restrict__ A1h, const __nv_bfloat16* __restrict__ A1l,
    const __nv_bfloat16* __restrict__ W1h, const __nv_bfloat16* __restrict__ W1l,
    const float* __restrict__ bias0, const float* __restrict__ bias1, int nph)
{
    extern __shared__ char smraw[];
    char* sm = (char*)(((unsigned long long)smraw + 1023ull) & ~1023ull);
    const uint32_t sb = smem_u32(sm);
    const uint32_t FULL = sb;          // NSTG x 8B
    const uint32_t DONE = sb + 64;     // NSTG x 8B
    const uint32_t STG0 = sb + 1024;

    const int tid = threadIdx.x;
    const int wid = tid >> 5, lane = tid & 31;
    const int nt = blockIdx.x;
    const int NCH = nph * KCHUNKS;
    const int wm = (wid & 3) * 32;     // warp M offset (0..96)
    const int wn = (wid >> 2) * 32;    // warp N offset within 64-tile (0 or 32)

    if (tid == 0) {
        for (int s = 0; s < NSTG; s++) { MBAR_INIT(FULL + 8 * s, 1); MBAR_INIT(DONE + 8 * s, 8); }
        asm volatile("fence.proxy.async.shared::cta;" ::: "memory");
    }
    __syncthreads();

    // prologue: fill all stages
    if (tid == 0) {
        for (int c = 0; c < NSTG && c < NCH; c++) {
            int p = (c >= KCHUNKS);
            int k = c - (p ? KCHUNKS : 0);
            const __nv_bfloat16* Ah = (p ? A1h : A0h) + (size_t)k * 8192;
            const __nv_bfloat16* Al = (p ? A1l : A0l) + (size_t)k * 8192;
            const __nv_bfloat16* Wh = (p ? W1h : W0h) + ((size_t)nt * KCHUNKS + k) * 4096;
            const __nv_bfloat16* Wl = (p ? W1l : W0l) + ((size_t)nt * KCHUNKS + k) * 4096;
            uint32_t st = STG0 + c * STAGE_B;
            MBAR_EXPECT_TX(FULL + 8 * c, STAGE_B);
            BULK_G2S(st,         Ah, 16384, FULL + 8 * c);
            BULK_G2S(st + 16384, Al, 16384, FULL + 8 * c);
            BULK_G2S(st + 32768, Wh,  8192, FULL + 8 * c);
            BULK_G2S(st + 40960, Wl,  8192, FULL + 8 * c);
        }
    }

    float acc[2][4][4];
#pragma unroll
    for (int i = 0; i < 2; i++)
#pragma unroll
        for (int jn = 0; jn < 4; jn++)
#pragma unroll
            for (int q = 0; q < 4; q++) acc[i][jn][q] = 0.f;

    // ldmatrix per-lane address components (x4: matrix b = lane/8, row = lane%8)
    const int a_row  = (lane & 7) + ((lane >> 3) & 1) * 8;  // A: b0/b2 rows 0-7, b1/b3 rows 8-15
    const int a_koff = (lane >> 4) * 16;                    // A: b0/b1 klow, b2/b3 khigh
    const int w_row  = (lane & 7) + ((lane >> 4) << 3);     // W: b0/b1 rows 0-7, b2/b3 rows 8-15
    const int w_koff = ((lane >> 3) & 1) * 16;              // W: b0/b2 klow, b1/b3 khigh

    for (int c = 0; c < NCH; c++) {
        int s = c & (NSTG - 1);
        MBAR_WAIT(FULL + 8 * s, (c >> 2) & 1);
        uint32_t stg = STG0 + s * STAGE_B;

#pragma unroll
        for (int kb = 0; kb < 4; kb++) {
            uint32_t ah[2][4], al[2][4], wh[2][4], wl[2][4];
#pragma unroll
            for (int mt = 0; mt < 2; mt++) {
                uint32_t ad = stg + sw128((uint32_t)((wm + mt * 16 + a_row) * 128 + kb * 32 + a_koff));
                LDSM4(ah[mt], ad);
                LDSM4(al[mt], ad + 16384);
            }
#pragma unroll
            for (int hf = 0; hf < 2; hf++) {
                uint32_t wd = stg + 32768 + sw128((uint32_t)((wn + hf * 16 + w_row) * 128 + kb * 32 + w_koff));
                LDSM4(wh[hf], wd);
                LDSM4(wl[hf], wd + 8192);
            }
#pragma unroll
            for (int mt = 0; mt < 2; mt++) {
#pragma unroll
                for (int hf = 0; hf < 2; hf++) {
                    MMA(acc[mt][2 * hf],     ah[mt], wh[hf][0], wh[hf][1]);
                    MMA(acc[mt][2 * hf + 1], ah[mt], wh[hf][2], wh[hf][3]);
                    MMA(acc[mt][2 * hf],     ah[mt], wl[hf][0], wl[hf][1]);
                    MMA(acc[mt][2 * hf + 1], ah[mt], wl[hf][2], wl[hf][3]);
                    MMA(acc[mt][2 * hf],     al[mt], wh[hf][0], wh[hf][1]);
                    MMA(acc[mt][2 * hf + 1], al[mt], wh[hf][2], wh[hf][3]);
                }
            }
        }
        __syncwarp();
        if (lane == 0) MBAR_ARRIVE(DONE + 8 * s);

        // refill stage s with chunk c+NSTG once all warps consumed chunk c
        int ncn = c + NSTG;
        if (tid == 0 && ncn < NCH) {
            MBAR_WAIT(DONE + 8 * s, (c >> 2) & 1);
            int p = (ncn >= KCHUNKS);
            int k = ncn - (p ? KCHUNKS : 0);
            const __nv_bfloat16* Ah = (p ? A1h : A0h) + (size_t)k * 8192;
            const __nv_bfloat16* Al = (p ? A1l : A0l) + (size_t)k * 8192;
            const __nv_bfloat16* Wh = (p ? W1h : W0h) + ((size_t)nt * KCHUNKS + k) * 4096;
            const __nv_bfloat16* Wl = (p ? W1l : W0l) + ((size_t)nt * KCHUNKS + k) * 4096;
            uint32_t st = STG0 + s * STAGE_B;
            MBAR_EXPECT_TX(FULL + 8 * s, STAGE_B);
            BULK_G2S(st,         Ah, 16384, FULL + 8 * s);
            BULK_G2S(st + 16384, Al, 16384, FULL + 8 * s);
            BULK_G2S(st + 32768, Wh,  8192, FULL + 8 * s);
            BULK_G2S(st + 40960, Wl,  8192, FULL + 8 * s);
        }
    }

    // epilogue: c-frag m16n8 layout — lane l: rows l/4, l/4+8; cols 2(l%4), +1
#pragma unroll
    for (int mt = 0; mt < 2; mt++) {
        int r0 = wm + mt * 16 + (lane >> 2);
        float* cp = C + (size_t)r0 * ldc;
#pragma unroll
        for (int ng = 0; ng < 4; ng++) {
            int col = nt * 64 + wn + ng * 8 + 2 * (lane & 3);
            float b0v = 0.f, b1v = 0.f;
            if (bias0) { b0v = bias0[col] + bias1[col]; b1v = bias0[col + 1] + bias1[col + 1]; }
            float2 v0 = make_float2(acc[mt][ng][0] + b0v, acc[mt][ng][1] + b1v);
            float2 v1 = make_float2(acc[mt][ng][2] + b0v, acc[mt][ng][3] + b1v);
            *(float2*)(cp + col) = v0;
            *(float2*)(cp + 8 * ldc + col) = v1;
        }
    }
}

// ---------------- LSTM cell: gates -> new c (fp32) + new h (swizzled hi/lo) ----------------
__global__ void __launch_bounds__(256) lstm_cell(
    const float* __restrict__ gates, float* __restrict__ c,
    __nv_bfloat16* __restrict__ hh, __nv_bfloat16* __restrict__ hl)
{
    int idx = blockIdx.x * 256 + threadIdx.x;   // < 128*1920
    int b = idx / H_;
    int jj = idx - b * H_;
    const float* g = gates + b * G4_;
    float ig = g[jj], fg = g[H_ + jj], gg = g[2 * H_ + jj], og = g[3 * H_ + jj];
    float si = 1.f / (1.f + expf(-ig));
    float sf = 1.f / (1.f + expf(-fg));
    float so = 1.f / (1.f + expf(-og));
    float tg = tanhf(gg);
    float cn = sf * c[idx] + si * tg;
    float hn = so * tanhf(cn);
    c[idx] = cn;
    uint32_t ai = act_idx(b, jj);
    __nv_bfloat16 hv = __float2bfloat16(hn);
    hh[ai] = hv;
    hl[ai] = __float2bfloat16(hn - __bfloat162float(hv));
}

// ---------------- W4 projection + residual + output write ----------------
__global__ void __launch_bounds__(128) w4_kernel(
    const float* __restrict__ r3, const float* __restrict__ b3,
    const float* __restrict__ W4, const float* __restrict__ b4,
    const float* __restrict__ inputs, float* __restrict__ out,
    int t, const int* __restrict__ burn)
{
    __shared__ __align__(16) float xs[H_];
    int b = blockIdx.x, tid = threadIdx.x;
    for (int k = tid; k < H_; k += 128) xs[k] = fmaxf(r3[b * H_ + k] + b3[k], 0.f);
    __syncthreads();
    if (tid < A_ * FIN_) {
        const float4* wp = (const float4*)(W4 + tid * H_);
        const float4* xp = (const float4*)xs;
        float a0 = 0.f, a1 = 0.f, a2 = 0.f, a3 = 0.f;
#pragma unroll 4
        for (int k = 0; k < H_ / 4; k++) {
            float4 w = wp[k]; float4 x = xp[k];
            a0 = fmaf(w.x, x.x, a0); a1 = fmaf(w.y, x.y, a1);
            a2 = fmaf(w.z, x.z, a2); a3 = fmaf(w.w, x.w, a3);
        }
        float acc = b4[tid] + (a0 + a1) + (a2 + a3);
        int a = tid >> 2, f = tid & 3;
        int r = b * A_ + a;
        int bi = burn ? *burn : 20;
        float insv = (t <= bi) ? inputs[(r * T_ + t) * FIN_ + f]
                               : out[(r * NSTEP + t - 1) * FIN_ + f];
        out[(r * NSTEP + t) * FIN_ + f] = acc + insv;
    }
}

// ---------------- launch ----------------
extern "C" void kernel_launch(void* const* d_in, const int* in_sizes, int n_in,
                              void* d_out, int out_size)
{
    const float* inputs = (const float*)d_in[0];
    const float* W1  = (const float*)d_in[1];
    const float* b1  = (const float*)d_in[2];
    const float* W2  = (const float*)d_in[3];
    const float* b2  = (const float*)d_in[4];
    const float* Wih = (const float*)d_in[5];
    const float* Whh = (const float*)d_in[6];
    const float* bih = (const float*)d_in[7];
    const float* bhh = (const float*)d_in[8];
    const float* W3  = (const float*)d_in[9];
    const float* b3  = (const float*)d_in[10];
    const float* W4  = (const float*)d_in[11];
    const float* b4  = (const float*)d_in[12];
    const int* burn  = (n_in > 14) ? (const int*)d_in[14] : nullptr;
    float* out = (float*)d_out;

    cudaFuncSetAttribute(gemm_mma, cudaFuncAttributeMaxDynamicSharedMemorySize, SMEMB);

    void *pwih_h, *pwih_l, *pwhh_h, *pwhh_l, *pw3_h, *pw3_l;
    void *pxh, *pxl, *ph0h, *ph0l, *ph1h, *ph1l, *pc, *pg, *pr;
    cudaGetSymbolAddress(&pwih_h, g_wih_h); cudaGetSymbolAddress(&pwih_l, g_wih_l);
    cudaGetSymbolAddress(&pwhh_h, g_whh_h); cudaGetSymbolAddress(&pwhh_l, g_whh_l);
    cudaGetSymbolAddress(&pw3_h, g_w3_h);   cudaGetSymbolAddress(&pw3_l, g_w3_l);
    cudaGetSymbolAddress(&pxh, g_xh);       cudaGetSymbolAddress(&pxl, g_xl);
    cudaGetSymbolAddress(&ph0h, g_h0h);     cudaGetSymbolAddress(&ph0l, g_h0l);
    cudaGetSymbolAddress(&ph1h, g_h1h);     cudaGetSymbolAddress(&ph1l, g_h1l);
    cudaGetSymbolAddress(&pc, g_c);
    cudaGetSymbolAddress(&pg, g_gates);
    cudaGetSymbolAddress(&pr, g_r3);

    __nv_bfloat16 *wih_h = (__nv_bfloat16*)pwih_h, *wih_l = (__nv_bfloat16*)pwih_l;
    __nv_bfloat16 *whh_h = (__nv_bfloat16*)pwhh_h, *whh_l = (__nv_bfloat16*)pwhh_l;
    __nv_bfloat16 *w3_h  = (__nv_bfloat16*)pw3_h,  *w3_l  = (__nv_bfloat16*)pw3_l;
    __nv_bfloat16 *xh = (__nv_bfloat16*)pxh,   *xl = (__nv_bfloat16*)pxl;
    __nv_bfloat16 *h0h = (__nv_bfloat16*)ph0h, *h0l = (__nv_bfloat16*)ph0l;
    __nv_bfloat16 *h1h = (__nv_bfloat16*)ph1h, *h1l = (__nv_bfloat16*)ph1l;
    float* c0 = (float*)pc;  float* c1 = c0 + B_ * H_;
    float* gates = (float*)pg;
    float* r3 = (float*)pr;

    // zero recurrent state
    cudaMemsetAsync(pc, 0, sizeof(float) * 2 * B_ * H_);
    cudaMemsetAsync(ph0h, 0, sizeof(__nv_bfloat16) * 245760);
    cudaMemsetAsync(ph0l, 0, sizeof(__nv_bfloat16) * 245760);
    cudaMemsetAsync(ph1h, 0, sizeof(__nv_bfloat16) * 245760);
    cudaMemsetAsync(ph1l, 0, sizeof(__nv_bfloat16) * 245760);

    // convert weights to pre-swizzled bf16 hi/lo 64x64 tiles (once per launch)
    const int TOT_IH = 2 * G4_ * H_;    // 29,491,200 rows-major [15360,1920]
    const int TOT_W3 = H_ * H_;         // 3,686,400
    conv_w<<<(TOT_IH + 255) / 256, 256>>>(Wih, wih_h, wih_l, TOT_IH, H_);
    conv_w<<<(TOT_IH + 255) / 256, 256>>>(Whh, whh_h, whh_l, TOT_IH, H_);
    conv_w<<<(TOT_W3 + 255) / 256, 256>>>(W3, w3_h, w3_l, TOT_W3, H_);

    for (int t = 0; t < NSTEP; t++) {
        mlp_kernel<<<960, dim3(64, 4)>>>(inputs, out, W1, b1, W2, b2, xh, xl, t, burn);

        // layer 0: gates = x@Wih0^T + h0@Whh0^T + bih0 + bhh0
        gemm_mma<<<G4_ / 64, 256, SMEMB>>>(gates, G4_,
            xh, xl, wih_h, wih_l,
            h0h, h0l, whh_h, whh_l,
            bih, bhh, 2);
        lstm_cell<<<960, 256>>>(gates, c0, h0h, h0l);

        // layer 1: gates = h0@Wih1^T + h1@Whh1^T + bih1 + bhh1
        gemm_mma<<<G4_ / 64, 256, SMEMB>>>(gates, G4_,
            h0h, h0l, wih_h + LOFF, wih_l + LOFF,
            h1h, h1l, whh_h + LOFF, whh_l + LOFF,
            bih + G4_, bhh + G4_, 2);
        lstm_cell<<<960, 256>>>(gates, c1, h1h, h1l);

        // W3: r3 = h1 @ W3^T (bias+relu applied in w4_kernel)
        gemm_mma<<<H_ / 64, 256, SMEMB>>>(r3, H_,
            h1h, h1l, w3_h, w3_l,
            nullptr, nullptr, nullptr, nullptr,
            nullptr, nullptr, 1);

        w4_kernel<<<B_, 128>>>(r3, b3, W4, b4, inputs, out, t, burn);
    }
}